// round 8
// baseline (speedup 1.0000x reference)
#include <cuda_runtime.h>
#include <cuda_bf16.h>

#define BB   16
#define NN   1024
#define FIN  256
#define FOUT 256
#define NEG_INF_V -1000000000.0f
#define SLOPE_V    0.2f

typedef unsigned long long u64;

// Scratch (allocation-free rule: __device__ globals)
__device__ float g_Wh[(size_t)BB * NN * FOUT];   // 64 MB
__device__ float g_f1[(size_t)BB * NN];
__device__ float g_f2[(size_t)BB * NN];
__device__ float g_m [(size_t)BB * NN];          // per-row softmax max

// ---- packed f32x2 helpers (FFMA2 only reachable via PTX) --------------------
__device__ __forceinline__ void ffma2(u64& d, u64 a, u64 b) {
    asm("fma.rn.f32x2 %0, %1, %2, %0;" : "+l"(d) : "l"(a), "l"(b));
}
__device__ __forceinline__ u64 pack2(float x, float y) {
    u64 r;
    asm("mov.b64 %0, {%1, %2};" : "=l"(r) : "f"(x), "f"(y));
    return r;
}
__device__ __forceinline__ float2 unpack2(u64 v) {
    float2 r;
    asm("mov.b64 {%0, %1}, %2;" : "=f"(r.x), "=f"(r.y) : "l"(v));
    return r;
}

// ---------------------------------------------------------------------------
// Kernel 1: Wh = h @ W.  M = B*N = 16384, K = 256, Nout = 256.
// 128x128 block tile, 16-deep K tiles, 8x8 register microtile per thread,
// FFMA2-packed along the j (output-channel) axis.
// ---------------------------------------------------------------------------
__global__ __launch_bounds__(256) void gemm_hW(const float* __restrict__ A,
                                               const float* __restrict__ Bm) {
    __shared__ __align__(16) float As[16][128];   // [k][m]
    __shared__ __align__(16) float Bs[16][128];   // [k][n]
    const int tid = threadIdx.x;
    const int m0 = blockIdx.y * 128;
    const int n0 = blockIdx.x * 128;
    const int tx = tid & 15;
    const int ty = tid >> 4;

    u64 acc2[8][4];   // [i][jpair] : channels (2jp, 2jp+1)
#pragma unroll
    for (int i = 0; i < 8; i++)
#pragma unroll
        for (int j = 0; j < 4; j++) acc2[i][j] = pack2(0.f, 0.f);

    for (int k0 = 0; k0 < FIN; k0 += 16) {
#pragma unroll
        for (int t = tid; t < 512; t += 256) {
            int m  = t >> 2;
            int kq = (t & 3) << 2;
            float4 v = *(const float4*)(A + (size_t)(m0 + m) * FIN + k0 + kq);
            As[kq + 0][m] = v.x;
            As[kq + 1][m] = v.y;
            As[kq + 2][m] = v.z;
            As[kq + 3][m] = v.w;
        }
#pragma unroll
        for (int t = tid; t < 512; t += 256) {
            int k  = t >> 5;
            int n4 = (t & 31) << 2;
            *(float4*)&Bs[k][n4] =
                *(const float4*)(Bm + (size_t)(k0 + k) * FOUT + n0 + n4);
        }
        __syncthreads();

#pragma unroll
        for (int k = 0; k < 16; k++) {
            float af[8];
            u64 b2[4];
            *(float4*)&af[0] = *(float4*)&As[k][ty * 8];
            *(float4*)&af[4] = *(float4*)&As[k][ty * 8 + 4];
            {   // B channel pairs straight from the 128-bit loads
                ulonglong2 p0 = *(ulonglong2*)&Bs[k][tx * 8];
                ulonglong2 p1 = *(ulonglong2*)&Bs[k][tx * 8 + 4];
                b2[0] = p0.x; b2[1] = p0.y; b2[2] = p1.x; b2[3] = p1.y;
            }
#pragma unroll
            for (int i = 0; i < 8; i++) {
                const u64 a2 = pack2(af[i], af[i]);
#pragma unroll
                for (int jp = 0; jp < 4; jp++) ffma2(acc2[i][jp], a2, b2[jp]);
            }
        }
        __syncthreads();
    }

#pragma unroll
    for (int i = 0; i < 8; i++) {
        float* orow = g_Wh + (size_t)(m0 + ty * 8 + i) * FOUT + n0 + tx * 8;
        float2 c0 = unpack2(acc2[i][0]), c1 = unpack2(acc2[i][1]);
        float2 c2 = unpack2(acc2[i][2]), c3 = unpack2(acc2[i][3]);
        *(float4*)orow       = make_float4(c0.x, c0.y, c1.x, c1.y);
        *(float4*)(orow + 4) = make_float4(c2.x, c2.y, c3.x, c3.y);
    }
}

// ---------------------------------------------------------------------------
// Kernel 1b: f1 = Wh @ a1, f2 = Wh @ a2.  One warp per row.
// ---------------------------------------------------------------------------
__global__ __launch_bounds__(256) void f12_kernel(const float* __restrict__ a) {
    const int w    = threadIdx.x >> 5;
    const int lane = threadIdx.x & 31;
    const int row  = blockIdx.x * 8 + w;
    const float* wh = g_Wh + (size_t)row * FOUT;
    float s1 = 0.f, s2 = 0.f;
#pragma unroll
    for (int k = 0; k < 8; k++) {
        int c = lane + 32 * k;
        float v = wh[c];
        s1 += v * a[c];
        s2 += v * a[FOUT + c];
    }
#pragma unroll
    for (int off = 16; off; off >>= 1) {
        s1 += __shfl_xor_sync(0xffffffffu, s1, off);
        s2 += __shfl_xor_sync(0xffffffffu, s2, off);
    }
    if (lane == 0) {
        g_f1[row] = s1;
        g_f2[row] = s2;
    }
}

// ---------------------------------------------------------------------------
// Kernel 1c: per-row softmax max via monotonicity of leaky_relu:
//   m_i = leaky_relu(f1_i + max_{j: adj_ij != 0} f2_j)
// ---------------------------------------------------------------------------
__global__ __launch_bounds__(256) void rowmax_kernel(const int* __restrict__ adj) {
    const int w    = threadIdx.x >> 5;
    const int lane = threadIdx.x & 31;
    const int b    = blockIdx.y;
    const int row  = blockIdx.x * 8 + w;

    const int4*  arow = (const int4*)(adj + ((size_t)b * NN + row) * NN);
    const float* f2b  = g_f2 + (size_t)b * NN;

    float m2 = -3.0e38f;
#pragma unroll
    for (int k = 0; k < 8; k++) {
        const int idx = lane + 32 * k;
        const int4   av = arow[idx];
        const float4 fv = *(const float4*)(f2b + idx * 4);
        if (av.x) m2 = fmaxf(m2, fv.x);
        if (av.y) m2 = fmaxf(m2, fv.y);
        if (av.z) m2 = fmaxf(m2, fv.z);
        if (av.w) m2 = fmaxf(m2, fv.w);
    }
#pragma unroll
    for (int off = 16; off; off >>= 1)
        m2 = fmaxf(m2, __shfl_xor_sync(0xffffffffu, m2, off));

    if (lane == 0) {
        float m;
        if (m2 == -3.0e38f) {
            m = NEG_INF_V;                         // isolated row -> uniform
        } else {
            const float s = g_f1[(size_t)b * NN + row] + m2;
            m = fmaxf(s, SLOPE_V * s);             // leaky_relu
        }
        g_m[(size_t)b * NN + row] = m;
    }
}

// ---------------------------------------------------------------------------
// Kernel 2: fused masked-softmax + attn@Wh, single pass, FFMA2-packed.
// Block = 8 warps; each warp owns 8 rows (64 rows/block, grid (16,16)).
// j in tiles of 32; Wh tile (32x256 f32 = 32KB) in SMEM shared by all warps.
// Lane l owns output channels [8l, 8l+8); channel-pair accumulators in b64;
// Wh pairs come straight from the 128-bit shared loads (no pack).
// ---------------------------------------------------------------------------
__global__ __launch_bounds__(256) void attn_kernel(const int* __restrict__ adj,
                                                   float* __restrict__ out) {
    __shared__ __align__(16) float whs[32][256];
    const int tid  = threadIdx.x;
    const int w    = tid >> 5;
    const int lane = tid & 31;
    const int b    = blockIdx.y;
    const int i0   = blockIdx.x * 64 + w * 8;

    const float* Whb  = g_Wh + (size_t)b * NN * FOUT;
    const int*   adjb = adj  + (size_t)b * NN * NN;
    const float* f2b  = g_f2 + (size_t)b * NN;

    u64 acc2[8][4];   // [row][chpair]
#pragma unroll
    for (int r = 0; r < 8; r++)
#pragma unroll
        for (int q = 0; q < 4; q++) acc2[r][q] = pack2(0.f, 0.f);

    float lsum[8], f1r[8], mr[8];
#pragma unroll
    for (int r = 0; r < 8; r++) {
        lsum[r] = 0.f;
        f1r[r]  = g_f1[(size_t)b * NN + i0 + r];
        mr[r]   = g_m [(size_t)b * NN + i0 + r];
    }

    for (int j0 = 0; j0 < NN; j0 += 32) {
        __syncthreads();   // protect whs from previous iteration's readers
#pragma unroll
        for (int t = tid; t < 2048; t += 256) {
            int j  = t >> 6;
            int c4 = (t & 63) << 2;
            *(float4*)&whs[j][c4] =
                *(const float4*)(Whb + (size_t)(j0 + j) * FOUT + c4);
        }
        __syncthreads();

        // scores for this tile: lane <-> column j0+lane
        const float f2v = f2b[j0 + lane];
        float pr[8];
#pragma unroll
        for (int r = 0; r < 8; r++) {
            const int i = i0 + r;
            float s = f1r[r] + f2v;
            float e = fmaxf(s, SLOPE_V * s);       // leaky_relu (slope<1)
            if (adjb[(size_t)i * NN + j0 + lane] == 0) e = NEG_INF_V;
            const float p = __expf(e - mr[r]);
            lsum[r] += p;
            pr[r] = p;
        }

        // acc[r][:] += p_j * Wh[j][:]   (packed channel pairs)
#pragma unroll
        for (int jj = 0; jj < 32; jj++) {
            const ulonglong2 w0 = *(const ulonglong2*)&whs[jj][lane << 3];
            const ulonglong2 w1 = *(const ulonglong2*)&whs[jj][(lane << 3) + 4];
#pragma unroll
            for (int r = 0; r < 8; r++) {
                const float pj = __shfl_sync(0xffffffffu, pr[r], jj);
                const u64 p2 = pack2(pj, pj);
                ffma2(acc2[r][0], p2, w0.x);
                ffma2(acc2[r][1], p2, w0.y);
                ffma2(acc2[r][2], p2, w1.x);
                ffma2(acc2[r][3], p2, w1.y);
            }
        }
    }

    // one warp-reduce of lsum per row, then scale + write
#pragma unroll
    for (int r = 0; r < 8; r++) {
        float s = lsum[r];
#pragma unroll
        for (int off = 16; off; off >>= 1)
            s += __shfl_xor_sync(0xffffffffu, s, off);
        const float inv = 1.f / s;
        float* orow = out + ((size_t)b * NN + i0 + r) * FOUT + (lane << 3);
        float2 c0 = unpack2(acc2[r][0]), c1 = unpack2(acc2[r][1]);
        float2 c2 = unpack2(acc2[r][2]), c3 = unpack2(acc2[r][3]);
        *(float4*)orow = make_float4(c0.x * inv, c0.y * inv, c1.x * inv, c1.y * inv);
        *(float4*)(orow + 4) =
            make_float4(c2.x * inv, c2.y * inv, c3.x * inv, c3.y * inv);
    }
}

// ---------------------------------------------------------------------------
extern "C" void kernel_launch(void* const* d_in, const int* in_sizes, int n_in,
                              void* d_out, int out_size) {
    const float* h   = (const float*)d_in[0];   // [16,1024,256] f32
    const int*   adj = (const int*)  d_in[1];   // [16,1024,1024] i32
    const float* W   = (const float*)d_in[2];   // [256,256] f32
    const float* a   = (const float*)d_in[3];   // [512] f32
    float* out = (float*)d_out;                 // [16,1024,256] f32

    dim3 g1(FOUT / 128, (BB * NN) / 128);       // (2, 128)
    gemm_hW<<<g1, 256>>>(h, W);

    f12_kernel<<<(BB * NN) / 8, 256>>>(a);

    dim3 gm(NN / 8, BB);                         // (128, 16)
    rowmax_kernel<<<gm, 256>>>(adj);

    dim3 g2(NN / 64, BB);                        // (16, 16)
    attn_kernel<<<g2, 256>>>(adj, out);
}

// round 13
// speedup vs baseline: 2.2770x; 2.2770x over previous
#include <cuda_runtime.h>
#include <cuda_fp16.h>
#include <cstdint>

#define BB   16
#define NN   1024
#define FIN  256
#define FOUT 256
#define NEG_INF_V -1000000000.0f
#define SLOPE_V    0.2f

// ---------------- scratch (__device__ globals; no allocations) --------------
__device__ float  g_Wh[(size_t)BB * NN * FOUT];            // 64 MB fp32
__device__ __half g_Wh16hi[(size_t)BB * NN * FOUT];        // 32 MB
__device__ __half g_Wh16lo[(size_t)BB * NN * FOUT];        // 32 MB
__device__ float  g_f1[(size_t)BB * NN];
__device__ float  g_f2[(size_t)BB * NN];
__device__ float  g_m [(size_t)BB * NN];

// ---------------- family-generic PTX helpers (sm_80+: valid on compute_103) -
__device__ __forceinline__ uint32_t smem_u32(const void* p) {
    uint32_t a;
    asm("{ .reg .u64 t; cvta.to.shared.u64 t, %1; cvt.u32.u64 %0, t; }"
        : "=r"(a) : "l"(p));
    return a;
}
__device__ __forceinline__ void ldsm4(uint32_t* r, uint32_t addr) {
    asm volatile("ldmatrix.sync.aligned.m8n8.x4.shared.b16 {%0,%1,%2,%3}, [%4];"
                 : "=r"(r[0]), "=r"(r[1]), "=r"(r[2]), "=r"(r[3]) : "r"(addr));
}
__device__ __forceinline__ void ldsm4t(uint32_t* r, uint32_t addr) {
    asm volatile("ldmatrix.sync.aligned.m8n8.x4.trans.shared.b16 {%0,%1,%2,%3}, [%4];"
                 : "=r"(r[0]), "=r"(r[1]), "=r"(r[2]), "=r"(r[3]) : "r"(addr));
}
__device__ __forceinline__ void mma_f16(float* d, const uint32_t* a,
                                        uint32_t b0, uint32_t b1) {
    asm volatile(
        "mma.sync.aligned.m16n8k16.row.col.f32.f16.f16.f32 "
        "{%0,%1,%2,%3}, {%4,%5,%6,%7}, {%8,%9}, {%0,%1,%2,%3};"
        : "+f"(d[0]), "+f"(d[1]), "+f"(d[2]), "+f"(d[3])
        : "r"(a[0]), "r"(a[1]), "r"(a[2]), "r"(a[3]), "r"(b0), "r"(b1));
}

// ---------------------------------------------------------------------------
// Kernel 1: Wh = h @ W (scalar fp32, R6-proven) + fp16 hi/lo split epilogue.
// ---------------------------------------------------------------------------
__global__ __launch_bounds__(256) void gemm_hW(const float* __restrict__ A,
                                               const float* __restrict__ Bm) {
    __shared__ float As[16][128];
    __shared__ float Bs[16][128];
    const int tid = threadIdx.x;
    const int m0 = blockIdx.y * 128;
    const int n0 = blockIdx.x * 128;
    const int tx = tid & 15;
    const int ty = tid >> 4;

    float acc[8][8];
#pragma unroll
    for (int i = 0; i < 8; i++)
#pragma unroll
        for (int j = 0; j < 8; j++) acc[i][j] = 0.f;

    for (int k0 = 0; k0 < FIN; k0 += 16) {
#pragma unroll
        for (int t = tid; t < 512; t += 256) {
            int m  = t >> 2;
            int kq = (t & 3) << 2;
            float4 v = *(const float4*)(A + (size_t)(m0 + m) * FIN + k0 + kq);
            As[kq + 0][m] = v.x;
            As[kq + 1][m] = v.y;
            As[kq + 2][m] = v.z;
            As[kq + 3][m] = v.w;
        }
#pragma unroll
        for (int t = tid; t < 512; t += 256) {
            int k  = t >> 5;
            int n4 = (t & 31) << 2;
            *(float4*)&Bs[k][n4] =
                *(const float4*)(Bm + (size_t)(k0 + k) * FOUT + n0 + n4);
        }
        __syncthreads();
#pragma unroll
        for (int k = 0; k < 16; k++) {
            float af[8], bf[8];
            *(float4*)&af[0] = *(float4*)&As[k][ty * 8];
            *(float4*)&af[4] = *(float4*)&As[k][ty * 8 + 4];
            *(float4*)&bf[0] = *(float4*)&Bs[k][tx * 8];
            *(float4*)&bf[4] = *(float4*)&Bs[k][tx * 8 + 4];
#pragma unroll
            for (int i = 0; i < 8; i++)
#pragma unroll
                for (int j = 0; j < 8; j++) acc[i][j] += af[i] * bf[j];
        }
        __syncthreads();
    }
#pragma unroll
    for (int i = 0; i < 8; i++) {
        const size_t row = (size_t)(m0 + ty * 8 + i);
        float* orow = g_Wh + row * FOUT + n0 + tx * 8;
        *(float4*)orow       = make_float4(acc[i][0], acc[i][1], acc[i][2], acc[i][3]);
        *(float4*)(orow + 4) = make_float4(acc[i][4], acc[i][5], acc[i][6], acc[i][7]);
        __half hh[8], hl[8];
#pragma unroll
        for (int q = 0; q < 8; q++) {
            hh[q] = __float2half_rn(acc[i][q]);
            hl[q] = __float2half_rn(acc[i][q] - __half2float(hh[q]));
        }
        uint4 hv, lv;
        {
            __half2 t0 = __halves2half2(hh[0], hh[1]), t1 = __halves2half2(hh[2], hh[3]);
            __half2 t2 = __halves2half2(hh[4], hh[5]), t3 = __halves2half2(hh[6], hh[7]);
            hv.x = *(uint32_t*)&t0; hv.y = *(uint32_t*)&t1;
            hv.z = *(uint32_t*)&t2; hv.w = *(uint32_t*)&t3;
        }
        {
            __half2 t0 = __halves2half2(hl[0], hl[1]), t1 = __halves2half2(hl[2], hl[3]);
            __half2 t2 = __halves2half2(hl[4], hl[5]), t3 = __halves2half2(hl[6], hl[7]);
            lv.x = *(uint32_t*)&t0; lv.y = *(uint32_t*)&t1;
            lv.z = *(uint32_t*)&t2; lv.w = *(uint32_t*)&t3;
        }
        *(uint4*)(g_Wh16hi + row * FOUT + n0 + tx * 8) = hv;
        *(uint4*)(g_Wh16lo + row * FOUT + n0 + tx * 8) = lv;
    }
}

// ---------------------------------------------------------------------------
// Kernel 1b: f1/f2 = Wh @ a1/a2
// ---------------------------------------------------------------------------
__global__ __launch_bounds__(256) void f12_kernel(const float* __restrict__ a) {
    const int w    = threadIdx.x >> 5;
    const int lane = threadIdx.x & 31;
    const int row  = blockIdx.x * 8 + w;
    const float* wh = g_Wh + (size_t)row * FOUT;
    float s1 = 0.f, s2 = 0.f;
#pragma unroll
    for (int k = 0; k < 8; k++) {
        int c = lane + 32 * k;
        float v = wh[c];
        s1 += v * a[c];
        s2 += v * a[FOUT + c];
    }
#pragma unroll
    for (int off = 16; off; off >>= 1) {
        s1 += __shfl_xor_sync(0xffffffffu, s1, off);
        s2 += __shfl_xor_sync(0xffffffffu, s2, off);
    }
    if (lane == 0) {
        g_f1[row] = s1;
        g_f2[row] = s2;
    }
}

// ---------------------------------------------------------------------------
// Kernel 1c: per-row softmax max (leaky_relu monotone)
// ---------------------------------------------------------------------------
__global__ __launch_bounds__(256) void rowmax_kernel(const int* __restrict__ adj) {
    const int w    = threadIdx.x >> 5;
    const int lane = threadIdx.x & 31;
    const int b    = blockIdx.y;
    const int row  = blockIdx.x * 8 + w;

    const int4*  arow = (const int4*)(adj + ((size_t)b * NN + row) * NN);
    const float* f2b  = g_f2 + (size_t)b * NN;

    float m2 = -3.0e38f;
#pragma unroll
    for (int k = 0; k < 8; k++) {
        const int idx = lane + 32 * k;
        const int4   av = arow[idx];
        const float4 fv = *(const float4*)(f2b + idx * 4);
        if (av.x) m2 = fmaxf(m2, fv.x);
        if (av.y) m2 = fmaxf(m2, fv.y);
        if (av.z) m2 = fmaxf(m2, fv.z);
        if (av.w) m2 = fmaxf(m2, fv.w);
    }
#pragma unroll
    for (int off = 16; off; off >>= 1)
        m2 = fmaxf(m2, __shfl_xor_sync(0xffffffffu, m2, off));

    if (lane == 0) {
        float m;
        if (m2 == -3.0e38f) {
            m = NEG_INF_V;
        } else {
            const float s = g_f1[(size_t)b * NN + row] + m2;
            m = fmaxf(s, SLOPE_V * s);
        }
        g_m[(size_t)b * NN + row] = m;
    }
}

// ---------------------------------------------------------------------------
// Kernel 2: warp-mma flash-GAT.
// Block: 256 thr = 8 warps (4 m-rows x 2 n-cols). 64 i-rows x 256 cols/block.
// 32 j-tiles of 32: stage Wh16 hi/lo tile + P(64x32) fp16 hi/lo in SMEM,
// ldmatrix -> mma.sync m16n8k16, 3-term split, fp32 accum in registers.
// SMEM: Whi 16K | Wlo 16K | Phi 4K | Plo 4K | lsum 256 = 41216 B (static).
// ---------------------------------------------------------------------------
#define S_WHI 0
#define S_WLO 16384
#define S_PHI 32768
#define S_PLO 36864
#define S_LS  40960

__global__ __launch_bounds__(256, 2) void attn_mma(const int* __restrict__ adj,
                                                   float* __restrict__ out) {
    __shared__ __align__(16) unsigned char sm[41216];
    const uint32_t sb = smem_u32(sm);
    const int tid  = threadIdx.x;
    const int lane = tid & 31;
    const int wid  = tid >> 5;
    const int wm   = wid >> 1;      // 0..3 : row block of 16
    const int wn   = wid & 1;       // 0..1 : col block of 128
    const int b    = blockIdx.y;
    const int i0   = blockIdx.x * 64;

    const int pr = tid >> 2;        // P-compute row 0..63
    const int pc = tid & 3;         // chunk of 8 j within 32-j tile
    const float f1r = g_f1[(size_t)b * NN + i0 + pr];
    const float mr  = g_m [(size_t)b * NN + i0 + pr];
    const int*   adjrow = adj + ((size_t)b * NN + i0 + pr) * NN;
    const float* f2b    = g_f2 + (size_t)b * NN;
    const __half* whH = g_Wh16hi + (size_t)b * NN * FOUT;
    const __half* whL = g_Wh16lo + (size_t)b * NN * FOUT;

    float acc[16][4];
#pragma unroll
    for (int n = 0; n < 16; n++)
#pragma unroll
        for (int q = 0; q < 4; q++) acc[n][q] = 0.f;
    float lsum = 0.f;

    const int jr = tid >> 3;        // Wh stage row 0..31
    const int cg = tid & 7;         // col group

    for (int tile = 0; tile < 32; tile++) {
        const int j0 = tile * 32;

        // ---- stage Wh hi/lo tile [32 j][256 c], swizzled ----
        {
            const __half* srcH = whH + (size_t)(j0 + jr) * FOUT;
            const __half* srcL = whL + (size_t)(j0 + jr) * FOUT;
#pragma unroll
            for (int u = 0; u < 4; u++) {
                const int ch = u * 8 + cg;                  // chunk 0..31 (8 f16)
                const uint32_t so = (uint32_t)jr * 512 + ((ch ^ (jr & 7)) << 4);
                *(uint4*)(sm + S_WHI + so) = *(const uint4*)(srcH + ch * 8);
                *(uint4*)(sm + S_WLO + so) = *(const uint4*)(srcL + ch * 8);
            }
        }

        // ---- compute P (8 values), split, store swizzled ----
        {
            const int jj = j0 + pc * 8;
            const int4   a0 = *(const int4*)(adjrow + jj);
            const int4   a1 = *(const int4*)(adjrow + jj + 4);
            const float4 fA = *(const float4*)(f2b + jj);
            const float4 fB = *(const float4*)(f2b + jj + 4);
            const float sv[8] = {fA.x, fA.y, fA.z, fA.w, fB.x, fB.y, fB.z, fB.w};
            const int   mk[8] = {a0.x, a0.y, a0.z, a0.w, a1.x, a1.y, a1.z, a1.w};
            __half ph[8], pl[8];
#pragma unroll
            for (int q = 0; q < 8; q++) {
                float s = f1r + sv[q];
                float e = fmaxf(s, SLOPE_V * s);
                if (mk[q] == 0) e = NEG_INF_V;
                const float p = __expf(e - mr);
                lsum += p;
                ph[q] = __float2half_rn(p);
                pl[q] = __float2half_rn(p - __half2float(ph[q]));
            }
            uint4 hv, lv;
            {
                __half2 t0 = __halves2half2(ph[0], ph[1]), t1 = __halves2half2(ph[2], ph[3]);
                __half2 t2 = __halves2half2(ph[4], ph[5]), t3 = __halves2half2(ph[6], ph[7]);
                hv.x = *(uint32_t*)&t0; hv.y = *(uint32_t*)&t1;
                hv.z = *(uint32_t*)&t2; hv.w = *(uint32_t*)&t3;
            }
            {
                __half2 t0 = __halves2half2(pl[0], pl[1]), t1 = __halves2half2(pl[2], pl[3]);
                __half2 t2 = __halves2half2(pl[4], pl[5]), t3 = __halves2half2(pl[6], pl[7]);
                lv.x = *(uint32_t*)&t0; lv.y = *(uint32_t*)&t1;
                lv.z = *(uint32_t*)&t2; lv.w = *(uint32_t*)&t3;
            }
            const uint32_t po = (uint32_t)pr * 64 + ((pc ^ (pr & 3)) << 4);
            *(uint4*)(sm + S_PHI + po) = hv;
            *(uint4*)(sm + S_PLO + po) = lv;
        }
        __syncthreads();

        // ---- MMA: 2 k16-steps x 8 col-groups x (3 split terms x 2 n8) ----
#pragma unroll
        for (int k = 0; k < 2; k++) {
            uint32_t ah[4], al[4];
            const int arow = wm * 16 + (lane & 15);
            const int ach  = k * 2 + (lane >> 4);
            const uint32_t ao = (uint32_t)arow * 64 + ((ach ^ (arow & 3)) << 4);
            ldsm4(ah, sb + S_PHI + ao);
            ldsm4(al, sb + S_PLO + ao);
            const int brow = k * 16 + (lane & 15);
#pragma unroll
            for (int g = 0; g < 8; g++) {
                const int nc = wn * 16 + g * 2 + (lane >> 4);
                const uint32_t bo = (uint32_t)brow * 512 + ((nc ^ (brow & 7)) << 4);
                uint32_t bh[4], bl[4];
                ldsm4t(bh, sb + S_WHI + bo);
                ldsm4t(bl, sb + S_WLO + bo);
                mma_f16(acc[2 * g],     ah, bh[0], bh[1]);
                mma_f16(acc[2 * g + 1], ah, bh[2], bh[3]);
                mma_f16(acc[2 * g],     al, bh[0], bh[1]);
                mma_f16(acc[2 * g + 1], al, bh[2], bh[3]);
                mma_f16(acc[2 * g],     ah, bl[0], bl[1]);
                mma_f16(acc[2 * g + 1], ah, bl[2], bl[3]);
            }
        }
        __syncthreads();
    }

    // ---- lsum: reduce over the 4 threads sharing a row ----
    {
        float s = lsum;
        s += __shfl_xor_sync(0xffffffffu, s, 1);
        s += __shfl_xor_sync(0xffffffffu, s, 2);
        if (pc == 0) *(float*)(sm + S_LS + pr * 4) = s;
    }
    __syncthreads();

    // ---- epilogue: scale by 1/lsum, write ----
    const int ra = wm * 16 + (lane >> 2);
    const float ia = 1.f / *(float*)(sm + S_LS + ra * 4);
    const float ib = 1.f / *(float*)(sm + S_LS + (ra + 8) * 4);
    float* outb = out + ((size_t)b * NN + i0) * FOUT;
#pragma unroll
    for (int nf = 0; nf < 16; nf++) {
        const int col = wn * 128 + nf * 8 + (lane & 3) * 2;
        *(float2*)(outb + (size_t)ra * FOUT + col) =
            make_float2(acc[nf][0] * ia, acc[nf][1] * ia);
        *(float2*)(outb + (size_t)(ra + 8) * FOUT + col) =
            make_float2(acc[nf][2] * ib, acc[nf][3] * ib);
    }
}

// ---------------------------------------------------------------------------
extern "C" void kernel_launch(void* const* d_in, const int* in_sizes, int n_in,
                              void* d_out, int out_size) {
    const float* h   = (const float*)d_in[0];   // [16,1024,256] f32
    const int*   adj = (const int*)  d_in[1];   // [16,1024,1024] i32
    const float* W   = (const float*)d_in[2];   // [256,256] f32
    const float* a   = (const float*)d_in[3];   // [512] f32
    float* out = (float*)d_out;                 // [16,1024,256] f32

    dim3 g1(FOUT / 128, (BB * NN) / 128);       // (2, 128)
    gemm_hW<<<g1, 256>>>(h, W);

    f12_kernel<<<(BB * NN) / 8, 256>>>(a);

    dim3 gm(NN / 8, BB);                         // (128, 16)
    rowmax_kernel<<<gm, 256>>>(adj);

    dim3 g2(NN / 64, BB);                        // (16, 16)
    attn_mma<<<g2, 256>>>(adj, out);
}

// round 14
// speedup vs baseline: 2.9232x; 1.2838x over previous
#include <cuda_runtime.h>
#include <cuda_fp16.h>
#include <cstdint>

#define BB   16
#define NN   1024
#define FIN  256
#define FOUT 256
#define NEG_INF_V -1000000000.0f
#define SLOPE_V    0.2f

// ---------------- scratch (__device__ globals; no allocations) --------------
__device__ __half g_Wh16hi[(size_t)BB * NN * FOUT];        // 32 MB
__device__ __half g_Wh16lo[(size_t)BB * NN * FOUT];        // 32 MB
__device__ float  g_f1[(size_t)BB * NN];
__device__ float  g_f2[(size_t)BB * NN];
__device__ float  g_m [(size_t)BB * NN];

// ---------------- family-generic PTX helpers (sm_80+: valid on compute_103) -
__device__ __forceinline__ uint32_t smem_u32(const void* p) {
    uint32_t a;
    asm("{ .reg .u64 t; cvta.to.shared.u64 t, %1; cvt.u32.u64 %0, t; }"
        : "=r"(a) : "l"(p));
    return a;
}
__device__ __forceinline__ void ldsm4(uint32_t* r, uint32_t addr) {
    asm volatile("ldmatrix.sync.aligned.m8n8.x4.shared.b16 {%0,%1,%2,%3}, [%4];"
                 : "=r"(r[0]), "=r"(r[1]), "=r"(r[2]), "=r"(r[3]) : "r"(addr));
}
__device__ __forceinline__ void ldsm4t(uint32_t* r, uint32_t addr) {
    asm volatile("ldmatrix.sync.aligned.m8n8.x4.trans.shared.b16 {%0,%1,%2,%3}, [%4];"
                 : "=r"(r[0]), "=r"(r[1]), "=r"(r[2]), "=r"(r[3]) : "r"(addr));
}
__device__ __forceinline__ void mma_f16(float* d, const uint32_t* a,
                                        uint32_t b0, uint32_t b1) {
    asm volatile(
        "mma.sync.aligned.m16n8k16.row.col.f32.f16.f16.f32 "
        "{%0,%1,%2,%3}, {%4,%5,%6,%7}, {%8,%9}, {%0,%1,%2,%3};"
        : "+f"(d[0]), "+f"(d[1]), "+f"(d[2]), "+f"(d[3])
        : "r"(a[0]), "r"(a[1]), "r"(a[2]), "r"(a[3]), "r"(b0), "r"(b1));
}
// split 8 fp32 -> packed hi/lo fp16 uint4s
__device__ __forceinline__ void split_pack8(const float* v, uint4& hv, uint4& lv) {
    __half hh[8], hl[8];
#pragma unroll
    for (int q = 0; q < 8; q++) {
        hh[q] = __float2half_rn(v[q]);
        hl[q] = __float2half_rn(v[q] - __half2float(hh[q]));
    }
    __half2 t0 = __halves2half2(hh[0], hh[1]), t1 = __halves2half2(hh[2], hh[3]);
    __half2 t2 = __halves2half2(hh[4], hh[5]), t3 = __halves2half2(hh[6], hh[7]);
    hv.x = *(uint32_t*)&t0; hv.y = *(uint32_t*)&t1;
    hv.z = *(uint32_t*)&t2; hv.w = *(uint32_t*)&t3;
    __half2 s0 = __halves2half2(hl[0], hl[1]), s1 = __halves2half2(hl[2], hl[3]);
    __half2 s2 = __halves2half2(hl[4], hl[5]), s3 = __halves2half2(hl[6], hl[7]);
    lv.x = *(uint32_t*)&s0; lv.y = *(uint32_t*)&s1;
    lv.z = *(uint32_t*)&s2; lv.w = *(uint32_t*)&s3;
}

// SMEM layout (shared by both mma kernels)
#define S_WHI 0
#define S_WLO 16384
#define S_PHI 32768
#define S_PLO 36864
#define S_LS  40960

// ---------------------------------------------------------------------------
// Kernel 1: Wh = h @ W via mma.sync, fp16 3-term split (hh+lh+hl), fp32 acc.
// Block = 64 m-rows x 256 n-cols, 8 warps as 2x4 (32 rows x 64 cols each).
// 8 k-tiles of 32; h tile split on the fly (A), W tile split on the fly (B).
// Epilogue writes Wh16 hi/lo directly (no fp32 Wh).
// ---------------------------------------------------------------------------
__global__ __launch_bounds__(256, 2) void gemm_mma(const float* __restrict__ A,
                                                   const float* __restrict__ W) {
    __shared__ __align__(16) unsigned char sm[40960];
    const uint32_t sb = smem_u32(sm);
    const int tid  = threadIdx.x;
    const int lane = tid & 31;
    const int wid  = tid >> 5;
    const int wm   = wid >> 2;      // 0..1 : 32-row block
    const int wn   = wid & 3;       // 0..3 : 64-col block
    const int i0   = blockIdx.x * 64;

    const int pr = tid >> 2, pc = tid & 3;   // A staging: row, 8-k chunk
    const int jr = tid >> 3, cg = tid & 7;   // B staging: k-row, col group

    float acc[16][4];
#pragma unroll
    for (int n = 0; n < 16; n++)
#pragma unroll
        for (int q = 0; q < 4; q++) acc[n][q] = 0.f;

    for (int kt = 0; kt < 8; kt++) {
        const int k0 = kt * 32;
        // ---- stage W tile [32 k][256 n] fp32 -> hi/lo, swizzled ----
        {
            const float* wsrc = W + (size_t)(k0 + jr) * FOUT;
#pragma unroll
            for (int u = 0; u < 4; u++) {
                const int ch = u * 8 + cg;
                float v[8];
                *(float4*)&v[0] = *(const float4*)(wsrc + ch * 8);
                *(float4*)&v[4] = *(const float4*)(wsrc + ch * 8 + 4);
                uint4 hv, lv;
                split_pack8(v, hv, lv);
                const uint32_t so = (uint32_t)jr * 512 + ((ch ^ (jr & 7)) << 4);
                *(uint4*)(sm + S_WHI + so) = hv;
                *(uint4*)(sm + S_WLO + so) = lv;
            }
        }
        // ---- stage h tile [64 m][32 k] fp32 -> hi/lo, swizzled ----
        {
            const float* asrc = A + (size_t)(i0 + pr) * FIN + k0 + pc * 8;
            float v[8];
            *(float4*)&v[0] = *(const float4*)asrc;
            *(float4*)&v[4] = *(const float4*)(asrc + 4);
            uint4 hv, lv;
            split_pack8(v, hv, lv);
            const uint32_t po = (uint32_t)pr * 64 + ((pc ^ (pr & 3)) << 4);
            *(uint4*)(sm + S_PHI + po) = hv;
            *(uint4*)(sm + S_PLO + po) = lv;
        }
        __syncthreads();

        // ---- MMA: 2 k16 x 2 mblk x 4 g x (3 terms x 2 n8) ----
#pragma unroll
        for (int k = 0; k < 2; k++) {
            uint32_t ah[2][4], al[2][4];
#pragma unroll
            for (int mb = 0; mb < 2; mb++) {
                const int arow = wm * 32 + mb * 16 + (lane & 15);
                const int ach  = k * 2 + (lane >> 4);
                const uint32_t ao = (uint32_t)arow * 64 + ((ach ^ (arow & 3)) << 4);
                ldsm4(ah[mb], sb + S_PHI + ao);
                ldsm4(al[mb], sb + S_PLO + ao);
            }
            const int brow = k * 16 + (lane & 15);
#pragma unroll
            for (int g = 0; g < 4; g++) {
                const int nc = wn * 8 + g * 2 + (lane >> 4);
                const uint32_t bo = (uint32_t)brow * 512 + ((nc ^ (brow & 7)) << 4);
                uint32_t bh[4], bl[4];
                ldsm4t(bh, sb + S_WHI + bo);
                ldsm4t(bl, sb + S_WLO + bo);
#pragma unroll
                for (int mb = 0; mb < 2; mb++) {
                    float* d0 = acc[mb * 8 + g * 2];
                    float* d1 = acc[mb * 8 + g * 2 + 1];
                    mma_f16(d0, ah[mb], bh[0], bh[1]);
                    mma_f16(d1, ah[mb], bh[2], bh[3]);
                    mma_f16(d0, al[mb], bh[0], bh[1]);
                    mma_f16(d1, al[mb], bh[2], bh[3]);
                    mma_f16(d0, ah[mb], bl[0], bl[1]);
                    mma_f16(d1, ah[mb], bl[2], bl[3]);
                }
            }
        }
        __syncthreads();
    }

    // ---- epilogue: split acc to fp16 hi/lo, store ----
#pragma unroll
    for (int mb = 0; mb < 2; mb++) {
        const int ra = wm * 32 + mb * 16 + (lane >> 2);
#pragma unroll
        for (int nf = 0; nf < 8; nf++) {
            const int col = wn * 64 + nf * 8 + (lane & 3) * 2;
            const float* d = acc[mb * 8 + nf];
#pragma unroll
            for (int hrow = 0; hrow < 2; hrow++) {
                const size_t off = (size_t)(i0 + ra + hrow * 8) * FOUT + col;
                const float v0 = d[hrow * 2], v1 = d[hrow * 2 + 1];
                const __half h0 = __float2half_rn(v0), h1 = __float2half_rn(v1);
                const __half l0 = __float2half_rn(v0 - __half2float(h0));
                const __half l1 = __float2half_rn(v1 - __half2float(h1));
                __half2 hp = __halves2half2(h0, h1);
                __half2 lp = __halves2half2(l0, l1);
                *(uint32_t*)(g_Wh16hi + off) = *(uint32_t*)&hp;
                *(uint32_t*)(g_Wh16lo + off) = *(uint32_t*)&lp;
            }
        }
    }
}

// ---------------------------------------------------------------------------
// Kernel 1b: f1/f2 = Wh @ a1/a2 (Wh reconstructed as hi+lo)
// ---------------------------------------------------------------------------
__global__ __launch_bounds__(256) void f12_kernel(const float* __restrict__ a) {
    const int w    = threadIdx.x >> 5;
    const int lane = threadIdx.x & 31;
    const int row  = blockIdx.x * 8 + w;
    const __half* whH = g_Wh16hi + (size_t)row * FOUT;
    const __half* whL = g_Wh16lo + (size_t)row * FOUT;
    float s1 = 0.f, s2 = 0.f;
#pragma unroll
    for (int k = 0; k < 8; k++) {
        int c = lane + 32 * k;
        float v = __half2float(whH[c]) + __half2float(whL[c]);
        s1 += v * a[c];
        s2 += v * a[FOUT + c];
    }
#pragma unroll
    for (int off = 16; off; off >>= 1) {
        s1 += __shfl_xor_sync(0xffffffffu, s1, off);
        s2 += __shfl_xor_sync(0xffffffffu, s2, off);
    }
    if (lane == 0) {
        g_f1[row] = s1;
        g_f2[row] = s2;
    }
}

// ---------------------------------------------------------------------------
// Kernel 1c: per-row softmax max (leaky_relu monotone)
// ---------------------------------------------------------------------------
__global__ __launch_bounds__(256) void rowmax_kernel(const int* __restrict__ adj) {
    const int w    = threadIdx.x >> 5;
    const int lane = threadIdx.x & 31;
    const int b    = blockIdx.y;
    const int row  = blockIdx.x * 8 + w;

    const int4*  arow = (const int4*)(adj + ((size_t)b * NN + row) * NN);
    const float* f2b  = g_f2 + (size_t)b * NN;

    float m2 = -3.0e38f;
#pragma unroll
    for (int k = 0; k < 8; k++) {
        const int idx = lane + 32 * k;
        const int4   av = arow[idx];
        const float4 fv = *(const float4*)(f2b + idx * 4);
        if (av.x) m2 = fmaxf(m2, fv.x);
        if (av.y) m2 = fmaxf(m2, fv.y);
        if (av.z) m2 = fmaxf(m2, fv.z);
        if (av.w) m2 = fmaxf(m2, fv.w);
    }
#pragma unroll
    for (int off = 16; off; off >>= 1)
        m2 = fmaxf(m2, __shfl_xor_sync(0xffffffffu, m2, off));

    if (lane == 0) {
        float m;
        if (m2 == -3.0e38f) {
            m = NEG_INF_V;
        } else {
            const float s = g_f1[(size_t)b * NN + row] + m2;
            m = fmaxf(s, SLOPE_V * s);
        }
        g_m[(size_t)b * NN + row] = m;
    }
}

// ---------------------------------------------------------------------------
// Kernel 2: warp-mma flash-GAT, 2x4 warp tiling (32 rows x 64 cols per warp)
// to halve redundant B ldmatrix traffic vs 4x2 (L1 was the binder at 60%).
// 64 i-rows x 256 cols per block; 32 j-tiles of 32.
// ---------------------------------------------------------------------------
__global__ __launch_bounds__(256, 2) void attn_mma(const int* __restrict__ adj,
                                                   float* __restrict__ out) {
    __shared__ __align__(16) unsigned char sm[41216];
    const uint32_t sb = smem_u32(sm);
    const int tid  = threadIdx.x;
    const int lane = tid & 31;
    const int wid  = tid >> 5;
    const int wm   = wid >> 2;      // 0..1 : 32-row block
    const int wn   = wid & 3;       // 0..3 : 64-col block
    const int b    = blockIdx.y;
    const int i0   = blockIdx.x * 64;

    const int pr = tid >> 2;        // P-compute row 0..63
    const int pc = tid & 3;         // chunk of 8 j within 32-j tile
    const float f1r = g_f1[(size_t)b * NN + i0 + pr];
    const float mr  = g_m [(size_t)b * NN + i0 + pr];
    const int*   adjrow = adj + ((size_t)b * NN + i0 + pr) * NN;
    const float* f2b    = g_f2 + (size_t)b * NN;
    const __half* whH = g_Wh16hi + (size_t)b * NN * FOUT;
    const __half* whL = g_Wh16lo + (size_t)b * NN * FOUT;

    float acc[16][4];
#pragma unroll
    for (int n = 0; n < 16; n++)
#pragma unroll
        for (int q = 0; q < 4; q++) acc[n][q] = 0.f;
    float lsum = 0.f;

    const int jr = tid >> 3;        // Wh stage row 0..31
    const int cg = tid & 7;         // col group

    for (int tile = 0; tile < 32; tile++) {
        const int j0 = tile * 32;

        // ---- stage Wh hi/lo tile [32 j][256 c], swizzled ----
        {
            const __half* srcH = whH + (size_t)(j0 + jr) * FOUT;
            const __half* srcL = whL + (size_t)(j0 + jr) * FOUT;
#pragma unroll
            for (int u = 0; u < 4; u++) {
                const int ch = u * 8 + cg;
                const uint32_t so = (uint32_t)jr * 512 + ((ch ^ (jr & 7)) << 4);
                *(uint4*)(sm + S_WHI + so) = *(const uint4*)(srcH + ch * 8);
                *(uint4*)(sm + S_WLO + so) = *(const uint4*)(srcL + ch * 8);
            }
        }

        // ---- compute P (8 values), split, store swizzled ----
        {
            const int jj = j0 + pc * 8;
            const int4   a0 = *(const int4*)(adjrow + jj);
            const int4   a1 = *(const int4*)(adjrow + jj + 4);
            const float4 fA = *(const float4*)(f2b + jj);
            const float4 fB = *(const float4*)(f2b + jj + 4);
            const float sv[8] = {fA.x, fA.y, fA.z, fA.w, fB.x, fB.y, fB.z, fB.w};
            const int   mk[8] = {a0.x, a0.y, a0.z, a0.w, a1.x, a1.y, a1.z, a1.w};
            float p[8];
#pragma unroll
            for (int q = 0; q < 8; q++) {
                float s = f1r + sv[q];
                float e = fmaxf(s, SLOPE_V * s);
                if (mk[q] == 0) e = NEG_INF_V;
                p[q] = __expf(e - mr);
                lsum += p[q];
            }
            uint4 hv, lv;
            split_pack8(p, hv, lv);
            const uint32_t po = (uint32_t)pr * 64 + ((pc ^ (pr & 3)) << 4);
            *(uint4*)(sm + S_PHI + po) = hv;
            *(uint4*)(sm + S_PLO + po) = lv;
        }
        __syncthreads();

        // ---- MMA: 2 k16 x 2 mblk x 4 g x (3 terms x 2 n8) ----
#pragma unroll
        for (int k = 0; k < 2; k++) {
            uint32_t ah[2][4], al[2][4];
#pragma unroll
            for (int mb = 0; mb < 2; mb++) {
                const int arow = wm * 32 + mb * 16 + (lane & 15);
                const int ach  = k * 2 + (lane >> 4);
                const uint32_t ao = (uint32_t)arow * 64 + ((ach ^ (arow & 3)) << 4);
                ldsm4(ah[mb], sb + S_PHI + ao);
                ldsm4(al[mb], sb + S_PLO + ao);
            }
            const int brow = k * 16 + (lane & 15);
#pragma unroll
            for (int g = 0; g < 4; g++) {
                const int nc = wn * 8 + g * 2 + (lane >> 4);
                const uint32_t bo = (uint32_t)brow * 512 + ((nc ^ (brow & 7)) << 4);
                uint32_t bh[4], bl[4];
                ldsm4t(bh, sb + S_WHI + bo);
                ldsm4t(bl, sb + S_WLO + bo);
#pragma unroll
                for (int mb = 0; mb < 2; mb++) {
                    float* d0 = acc[mb * 8 + g * 2];
                    float* d1 = acc[mb * 8 + g * 2 + 1];
                    mma_f16(d0, ah[mb], bh[0], bh[1]);
                    mma_f16(d1, ah[mb], bh[2], bh[3]);
                    mma_f16(d0, al[mb], bh[0], bh[1]);
                    mma_f16(d1, al[mb], bh[2], bh[3]);
                    mma_f16(d0, ah[mb], bl[0], bl[1]);
                    mma_f16(d1, ah[mb], bl[2], bl[3]);
                }
            }
        }
        __syncthreads();
    }

    // ---- lsum: reduce over the 4 threads sharing a row ----
    {
        float s = lsum;
        s += __shfl_xor_sync(0xffffffffu, s, 1);
        s += __shfl_xor_sync(0xffffffffu, s, 2);
        if (pc == 0) *(float*)(sm + S_LS + pr * 4) = s;
    }
    __syncthreads();

    // ---- epilogue: scale by 1/lsum, write ----
    float* outb = out + ((size_t)b * NN + i0) * FOUT;
#pragma unroll
    for (int mb = 0; mb < 2; mb++) {
        const int ra = wm * 32 + mb * 16 + (lane >> 2);
        const float ia = 1.f / *(float*)(sm + S_LS + ra * 4);
        const float ib = 1.f / *(float*)(sm + S_LS + (ra + 8) * 4);
#pragma unroll
        for (int nf = 0; nf < 8; nf++) {
            const int col = wn * 64 + nf * 8 + (lane & 3) * 2;
            const float* d = acc[mb * 8 + nf];
            *(float2*)(outb + (size_t)ra * FOUT + col) =
                make_float2(d[0] * ia, d[1] * ia);
            *(float2*)(outb + (size_t)(ra + 8) * FOUT + col) =
                make_float2(d[2] * ib, d[3] * ib);
        }
    }
}

// ---------------------------------------------------------------------------
extern "C" void kernel_launch(void* const* d_in, const int* in_sizes, int n_in,
                              void* d_out, int out_size) {
    const float* h   = (const float*)d_in[0];   // [16,1024,256] f32
    const int*   adj = (const int*)  d_in[1];   // [16,1024,1024] i32
    const float* W   = (const float*)d_in[2];   // [256,256] f32
    const float* a   = (const float*)d_in[3];   // [512] f32
    float* out = (float*)d_out;                 // [16,1024,256] f32

    gemm_mma<<<(BB * NN) / 64, 256>>>(h, W);    // 256 blocks

    f12_kernel<<<(BB * NN) / 8, 256>>>(a);

    dim3 gm(NN / 8, BB);                         // (128, 16)
    rowmax_kernel<<<gm, 256>>>(adj);

    dim3 g2(NN / 64, BB);                        // (16, 16)
    attn_mma<<<g2, 256>>>(adj, out);
}

// round 16
// speedup vs baseline: 3.4819x; 1.1911x over previous
#include <cuda_runtime.h>
#include <cuda_fp16.h>
#include <cstdint>

#define BB   16
#define NN   1024
#define FIN  256
#define FOUT 256
#define NEG_INF_V -1000000000.0f
#define SLOPE_V    0.2f

// ---------------- scratch (__device__ globals; no allocations) --------------
__device__ __half g_Wh16hi[(size_t)BB * NN * FOUT];        // 32 MB
__device__ __half g_Wh16lo[(size_t)BB * NN * FOUT];        // 32 MB
__device__ float  g_f1[(size_t)BB * NN];
__device__ float  g_f2[(size_t)BB * NN];
__device__ float  g_m [(size_t)BB * NN];

// ---------------- family-generic PTX helpers (sm_80+: valid on compute_103) -
__device__ __forceinline__ uint32_t smem_u32(const void* p) {
    uint32_t a;
    asm("{ .reg .u64 t; cvta.to.shared.u64 t, %1; cvt.u32.u64 %0, t; }"
        : "=r"(a) : "l"(p));
    return a;
}
__device__ __forceinline__ void ldsm4(uint32_t* r, uint32_t addr) {
    asm volatile("ldmatrix.sync.aligned.m8n8.x4.shared.b16 {%0,%1,%2,%3}, [%4];"
                 : "=r"(r[0]), "=r"(r[1]), "=r"(r[2]), "=r"(r[3]) : "r"(addr));
}
__device__ __forceinline__ void ldsm4t(uint32_t* r, uint32_t addr) {
    asm volatile("ldmatrix.sync.aligned.m8n8.x4.trans.shared.b16 {%0,%1,%2,%3}, [%4];"
                 : "=r"(r[0]), "=r"(r[1]), "=r"(r[2]), "=r"(r[3]) : "r"(addr));
}
__device__ __forceinline__ void mma_f16(float* d, const uint32_t* a,
                                        uint32_t b0, uint32_t b1) {
    asm volatile(
        "mma.sync.aligned.m16n8k16.row.col.f32.f16.f16.f32 "
        "{%0,%1,%2,%3}, {%4,%5,%6,%7}, {%8,%9}, {%0,%1,%2,%3};"
        : "+f"(d[0]), "+f"(d[1]), "+f"(d[2]), "+f"(d[3])
        : "r"(a[0]), "r"(a[1]), "r"(a[2]), "r"(a[3]), "r"(b0), "r"(b1));
}
// split 8 fp32 -> packed hi/lo fp16 uint4s
__device__ __forceinline__ void split_pack8(const float* v, uint4& hv, uint4& lv) {
    __half hh[8], hl[8];
#pragma unroll
    for (int q = 0; q < 8; q++) {
        hh[q] = __float2half_rn(v[q]);
        hl[q] = __float2half_rn(v[q] - __half2float(hh[q]));
    }
    __half2 t0 = __halves2half2(hh[0], hh[1]), t1 = __halves2half2(hh[2], hh[3]);
    __half2 t2 = __halves2half2(hh[4], hh[5]), t3 = __halves2half2(hh[6], hh[7]);
    hv.x = *(uint32_t*)&t0; hv.y = *(uint32_t*)&t1;
    hv.z = *(uint32_t*)&t2; hv.w = *(uint32_t*)&t3;
    __half2 s0 = __halves2half2(hl[0], hl[1]), s1 = __halves2half2(hl[2], hl[3]);
    __half2 s2 = __halves2half2(hl[4], hl[5]), s3 = __halves2half2(hl[6], hl[7]);
    lv.x = *(uint32_t*)&s0; lv.y = *(uint32_t*)&s1;
    lv.z = *(uint32_t*)&s2; lv.w = *(uint32_t*)&s3;
}
// pack 8 fp32 -> fp16 (hi only)
__device__ __forceinline__ void pack8h(const float* v, uint4& hv) {
    __half2 t0 = __floats2half2_rn(v[0], v[1]);
    __half2 t1 = __floats2half2_rn(v[2], v[3]);
    __half2 t2 = __floats2half2_rn(v[4], v[5]);
    __half2 t3 = __floats2half2_rn(v[6], v[7]);
    hv.x = *(uint32_t*)&t0; hv.y = *(uint32_t*)&t1;
    hv.z = *(uint32_t*)&t2; hv.w = *(uint32_t*)&t3;
}

// SMEM layout
#define S_WHI 0
#define S_WLO 16384
#define S_PHI 32768
#define S_PLO 36864          // gemm only
#define S_LS  36864          // attn: lsum region (P_lo dropped)
#define S_F12 0              // gemm epilogue reuse: 64 x float2

// ---------------------------------------------------------------------------
// Kernel 1: Wh = h @ W via mma.sync (3-term split), fp32 acc. Fused epilogue:
// writes Wh16 hi/lo AND f1/f2 (fp32-accurate dot with a1/a2).
// Block = 64 m-rows x 256 n-cols, 8 warps as 2x4.
// ---------------------------------------------------------------------------
__global__ __launch_bounds__(256, 2) void gemm_mma(const float* __restrict__ A,
                                                   const float* __restrict__ W,
                                                   const float* __restrict__ avec) {
    __shared__ __align__(16) unsigned char sm[40960];
    const uint32_t sb = smem_u32(sm);
    const int tid  = threadIdx.x;
    const int lane = tid & 31;
    const int wid  = tid >> 5;
    const int wm   = wid >> 2;      // 0..1 : 32-row block
    const int wn   = wid & 3;       // 0..3 : 64-col block
    const int i0   = blockIdx.x * 64;

    const int pr = tid >> 2, pc = tid & 3;   // A staging: row, 8-k chunk
    const int jr = tid >> 3, cg = tid & 7;   // B staging: k-row, col group

    float acc[16][4];
#pragma unroll
    for (int n = 0; n < 16; n++)
#pragma unroll
        for (int q = 0; q < 4; q++) acc[n][q] = 0.f;

    for (int kt = 0; kt < 8; kt++) {
        const int k0 = kt * 32;
        // ---- stage W tile [32 k][256 n] fp32 -> hi/lo, swizzled ----
        {
            const float* wsrc = W + (size_t)(k0 + jr) * FOUT;
#pragma unroll
            for (int u = 0; u < 4; u++) {
                const int ch = u * 8 + cg;
                float v[8];
                *(float4*)&v[0] = *(const float4*)(wsrc + ch * 8);
                *(float4*)&v[4] = *(const float4*)(wsrc + ch * 8 + 4);
                uint4 hv, lv;
                split_pack8(v, hv, lv);
                const uint32_t so = (uint32_t)jr * 512 + ((ch ^ (jr & 7)) << 4);
                *(uint4*)(sm + S_WHI + so) = hv;
                *(uint4*)(sm + S_WLO + so) = lv;
            }
        }
        // ---- stage h tile [64 m][32 k] fp32 -> hi/lo, swizzled ----
        {
            const float* asrc = A + (size_t)(i0 + pr) * FIN + k0 + pc * 8;
            float v[8];
            *(float4*)&v[0] = *(const float4*)asrc;
            *(float4*)&v[4] = *(const float4*)(asrc + 4);
            uint4 hv, lv;
            split_pack8(v, hv, lv);
            const uint32_t po = (uint32_t)pr * 64 + ((pc ^ (pr & 3)) << 4);
            *(uint4*)(sm + S_PHI + po) = hv;
            *(uint4*)(sm + S_PLO + po) = lv;
        }
        __syncthreads();

        // ---- MMA: 2 k16 x 2 mblk x 4 g x (3 terms x 2 n8) ----
#pragma unroll
        for (int k = 0; k < 2; k++) {
            uint32_t ah[2][4], al[2][4];
#pragma unroll
            for (int mb = 0; mb < 2; mb++) {
                const int arow = wm * 32 + mb * 16 + (lane & 15);
                const int ach  = k * 2 + (lane >> 4);
                const uint32_t ao = (uint32_t)arow * 64 + ((ach ^ (arow & 3)) << 4);
                ldsm4(ah[mb], sb + S_PHI + ao);
                ldsm4(al[mb], sb + S_PLO + ao);
            }
            const int brow = k * 16 + (lane & 15);
#pragma unroll
            for (int g = 0; g < 4; g++) {
                const int nc = wn * 8 + g * 2 + (lane >> 4);
                const uint32_t bo = (uint32_t)brow * 512 + ((nc ^ (brow & 7)) << 4);
                uint32_t bh[4], bl[4];
                ldsm4t(bh, sb + S_WHI + bo);
                ldsm4t(bl, sb + S_WLO + bo);
#pragma unroll
                for (int mb = 0; mb < 2; mb++) {
                    float* d0 = acc[mb * 8 + g * 2];
                    float* d1 = acc[mb * 8 + g * 2 + 1];
                    mma_f16(d0, ah[mb], bh[0], bh[1]);
                    mma_f16(d1, ah[mb], bh[2], bh[3]);
                    mma_f16(d0, al[mb], bh[0], bh[1]);
                    mma_f16(d1, al[mb], bh[2], bh[3]);
                    mma_f16(d0, ah[mb], bl[0], bl[1]);
                    mma_f16(d1, ah[mb], bl[2], bl[3]);
                }
            }
        }
        __syncthreads();
    }

    // ---- epilogue A: split acc to fp16 hi/lo, store Wh16 ----
#pragma unroll
    for (int mb = 0; mb < 2; mb++) {
        const int ra = wm * 32 + mb * 16 + (lane >> 2);
#pragma unroll
        for (int nf = 0; nf < 8; nf++) {
            const int col = wn * 64 + nf * 8 + (lane & 3) * 2;
            const float* d = acc[mb * 8 + nf];
#pragma unroll
            for (int hrow = 0; hrow < 2; hrow++) {
                const size_t off = (size_t)(i0 + ra + hrow * 8) * FOUT + col;
                const float v0 = d[hrow * 2], v1 = d[hrow * 2 + 1];
                const __half h0 = __float2half_rn(v0), h1 = __float2half_rn(v1);
                const __half l0 = __float2half_rn(v0 - __half2float(h0));
                const __half l1 = __float2half_rn(v1 - __half2float(h1));
                __half2 hp = __halves2half2(h0, h1);
                __half2 lp = __halves2half2(l0, l1);
                *(uint32_t*)(g_Wh16hi + off) = *(uint32_t*)&hp;
                *(uint32_t*)(g_Wh16lo + off) = *(uint32_t*)&lp;
            }
        }
    }

    // ---- epilogue B: fused f1/f2 = Wh @ a1/a2 from fp32 accumulators ----
    float* sf = (float*)(sm + S_F12);            // [64][2], reuse (post-sync)
    if (tid < 128) sf[tid] = 0.f;
    __syncthreads();
#pragma unroll
    for (int mb = 0; mb < 2; mb++) {
#pragma unroll
        for (int hrow = 0; hrow < 2; hrow++) {
            float s1 = 0.f, s2 = 0.f;
#pragma unroll
            for (int nf = 0; nf < 8; nf++) {
                const int col = wn * 64 + nf * 8 + (lane & 3) * 2;
                const float* d = acc[mb * 8 + nf];
                s1 += d[hrow * 2] * avec[col] + d[hrow * 2 + 1] * avec[col + 1];
                s2 += d[hrow * 2] * avec[FOUT + col] +
                      d[hrow * 2 + 1] * avec[FOUT + col + 1];
            }
            s1 += __shfl_xor_sync(0xffffffffu, s1, 1);
            s1 += __shfl_xor_sync(0xffffffffu, s1, 2);
            s2 += __shfl_xor_sync(0xffffffffu, s2, 1);
            s2 += __shfl_xor_sync(0xffffffffu, s2, 2);
            if ((lane & 3) == 0) {
                const int row = wm * 32 + mb * 16 + hrow * 8 + (lane >> 2);
                atomicAdd(&sf[row * 2 + 0], s1);
                atomicAdd(&sf[row * 2 + 1], s2);
            }
        }
    }
    __syncthreads();
    if (tid < 64) {
        g_f1[i0 + tid] = sf[tid * 2 + 0];
        g_f2[i0 + tid] = sf[tid * 2 + 1];
    }
}

// ---------------------------------------------------------------------------
// Kernel 1c: per-row softmax max (leaky_relu monotone)
// ---------------------------------------------------------------------------
__global__ __launch_bounds__(256) void rowmax_kernel(const int* __restrict__ adj) {
    const int w    = threadIdx.x >> 5;
    const int lane = threadIdx.x & 31;
    const int b    = blockIdx.y;
    const int row  = blockIdx.x * 8 + w;

    const int4*  arow = (const int4*)(adj + ((size_t)b * NN + row) * NN);
    const float* f2b  = g_f2 + (size_t)b * NN;

    float m2 = -3.0e38f;
#pragma unroll
    for (int k = 0; k < 8; k++) {
        const int idx = lane + 32 * k;
        const int4   av = arow[idx];
        const float4 fv = *(const float4*)(f2b + idx * 4);
        if (av.x) m2 = fmaxf(m2, fv.x);
        if (av.y) m2 = fmaxf(m2, fv.y);
        if (av.z) m2 = fmaxf(m2, fv.z);
        if (av.w) m2 = fmaxf(m2, fv.w);
    }
#pragma unroll
    for (int off = 16; off; off >>= 1)
        m2 = fmaxf(m2, __shfl_xor_sync(0xffffffffu, m2, off));

    if (lane == 0) {
        float m;
        if (m2 == -3.0e38f) {
            m = NEG_INF_V;
        } else {
            const float s = g_f1[(size_t)b * NN + row] + m2;
            m = fmaxf(s, SLOPE_V * s);
        }
        g_m[(size_t)b * NN + row] = m;
    }
}

// ---------------------------------------------------------------------------
// Kernel 2: warp-mma flash-GAT, 2-term (P fp16-hi only; Wh hi+lo).
// 2x4 warp tiling; 64 i-rows x 256 cols per block; 32 j-tiles of 32.
// Per tile per warp: 4 ldsm A, 16 ldsm B, 64 mma (was 8/16/96).
// ---------------------------------------------------------------------------
__global__ __launch_bounds__(256, 2) void attn_mma(const int* __restrict__ adj,
                                                   float* __restrict__ out) {
    __shared__ __align__(16) unsigned char sm[37376];
    const uint32_t sb = smem_u32(sm);
    const int tid  = threadIdx.x;
    const int lane = tid & 31;
    const int wid  = tid >> 5;
    const int wm   = wid >> 2;      // 0..1 : 32-row block
    const int wn   = wid & 3;       // 0..3 : 64-col block
    const int b    = blockIdx.y;
    const int i0   = blockIdx.x * 64;

    const int pr = tid >> 2;        // P-compute row 0..63
    const int pc = tid & 3;         // chunk of 8 j within 32-j tile
    const float f1r = g_f1[(size_t)b * NN + i0 + pr];
    const float mr  = g_m [(size_t)b * NN + i0 + pr];
    const int*   adjrow = adj + ((size_t)b * NN + i0 + pr) * NN;
    const float* f2b    = g_f2 + (size_t)b * NN;
    const __half* whH = g_Wh16hi + (size_t)b * NN * FOUT;
    const __half* whL = g_Wh16lo + (size_t)b * NN * FOUT;

    float acc[16][4];
#pragma unroll
    for (int n = 0; n < 16; n++)
#pragma unroll
        for (int q = 0; q < 4; q++) acc[n][q] = 0.f;
    float lsum = 0.f;

    const int jr = tid >> 3;        // Wh stage row 0..31
    const int cg = tid & 7;         // col group

    for (int tile = 0; tile < 32; tile++) {
        const int j0 = tile * 32;

        // ---- stage Wh hi/lo tile [32 j][256 c], swizzled ----
        {
            const __half* srcH = whH + (size_t)(j0 + jr) * FOUT;
            const __half* srcL = whL + (size_t)(j0 + jr) * FOUT;
#pragma unroll
            for (int u = 0; u < 4; u++) {
                const int ch = u * 8 + cg;
                const uint32_t so = (uint32_t)jr * 512 + ((ch ^ (jr & 7)) << 4);
                *(uint4*)(sm + S_WHI + so) = *(const uint4*)(srcH + ch * 8);
                *(uint4*)(sm + S_WLO + so) = *(const uint4*)(srcL + ch * 8);
            }
        }

        // ---- compute P (8 values), pack fp16-hi, store swizzled ----
        {
            const int jj = j0 + pc * 8;
            const int4   a0 = *(const int4*)(adjrow + jj);
            const int4   a1 = *(const int4*)(adjrow + jj + 4);
            const float4 fA = *(const float4*)(f2b + jj);
            const float4 fB = *(const float4*)(f2b + jj + 4);
            const float sv[8] = {fA.x, fA.y, fA.z, fA.w, fB.x, fB.y, fB.z, fB.w};
            const int   mk[8] = {a0.x, a0.y, a0.z, a0.w, a1.x, a1.y, a1.z, a1.w};
            float p[8];
#pragma unroll
            for (int q = 0; q < 8; q++) {
                float s = f1r + sv[q];
                float e = fmaxf(s, SLOPE_V * s);
                if (mk[q] == 0) e = NEG_INF_V;
                p[q] = __expf(e - mr);
                lsum += p[q];
            }
            uint4 hv;
            pack8h(p, hv);
            const uint32_t po = (uint32_t)pr * 64 + ((pc ^ (pr & 3)) << 4);
            *(uint4*)(sm + S_PHI + po) = hv;
        }
        __syncthreads();

        // ---- MMA: 2 k16 x 2 mblk x 4 g x (2 terms x 2 n8) ----
#pragma unroll
        for (int k = 0; k < 2; k++) {
            uint32_t ah[2][4];
#pragma unroll
            for (int mb = 0; mb < 2; mb++) {
                const int arow = wm * 32 + mb * 16 + (lane & 15);
                const int ach  = k * 2 + (lane >> 4);
                const uint32_t ao = (uint32_t)arow * 64 + ((ach ^ (arow & 3)) << 4);
                ldsm4(ah[mb], sb + S_PHI + ao);
            }
            const int brow = k * 16 + (lane & 15);
#pragma unroll
            for (int g = 0; g < 4; g++) {
                const int nc = wn * 8 + g * 2 + (lane >> 4);
                const uint32_t bo = (uint32_t)brow * 512 + ((nc ^ (brow & 7)) << 4);
                uint32_t bh[4], bl[4];
                ldsm4t(bh, sb + S_WHI + bo);
                ldsm4t(bl, sb + S_WLO + bo);
#pragma unroll
                for (int mb = 0; mb < 2; mb++) {
                    float* d0 = acc[mb * 8 + g * 2];
                    float* d1 = acc[mb * 8 + g * 2 + 1];
                    mma_f16(d0, ah[mb], bh[0], bh[1]);
                    mma_f16(d1, ah[mb], bh[2], bh[3]);
                    mma_f16(d0, ah[mb], bl[0], bl[1]);
                    mma_f16(d1, ah[mb], bl[2], bl[3]);
                }
            }
        }
        __syncthreads();
    }

    // ---- lsum: reduce over the 4 threads sharing a row ----
    {
        float s = lsum;
        s += __shfl_xor_sync(0xffffffffu, s, 1);
        s += __shfl_xor_sync(0xffffffffu, s, 2);
        if (pc == 0) *(float*)(sm + S_LS + pr * 4) = s;
    }
    __syncthreads();

    // ---- epilogue: scale by 1/lsum, write ----
    float* outb = out + ((size_t)b * NN + i0) * FOUT;
#pragma unroll
    for (int mb = 0; mb < 2; mb++) {
        const int ra = wm * 32 + mb * 16 + (lane >> 2);
        const float ia = 1.f / *(float*)(sm + S_LS + ra * 4);
        const float ib = 1.f / *(float*)(sm + S_LS + (ra + 8) * 4);
#pragma unroll
        for (int nf = 0; nf < 8; nf++) {
            const int col = wn * 64 + nf * 8 + (lane & 3) * 2;
            const float* d = acc[mb * 8 + nf];
            *(float2*)(outb + (size_t)ra * FOUT + col) =
                make_float2(d[0] * ia, d[1] * ia);
            *(float2*)(outb + (size_t)(ra + 8) * FOUT + col) =
                make_float2(d[2] * ib, d[3] * ib);
        }
    }
}

// ---------------------------------------------------------------------------
extern "C" void kernel_launch(void* const* d_in, const int* in_sizes, int n_in,
                              void* d_out, int out_size) {
    const float* h   = (const float*)d_in[0];   // [16,1024,256] f32
    const int*   adj = (const int*)  d_in[1];   // [16,1024,1024] i32
    const float* W   = (const float*)d_in[2];   // [256,256] f32
    const float* a   = (const float*)d_in[3];   // [512] f32
    float* out = (float*)d_out;                 // [16,1024,256] f32

    gemm_mma<<<(BB * NN) / 64, 256>>>(h, W, a); // 256 blocks, f12 fused

    dim3 gm(NN / 8, BB);                         // (128, 16)
    rowmax_kernel<<<gm, 256>>>(adj);

    dim3 g2(NN / 64, BB);                        // (16, 16)
    attn_mma<<<g2, 256>>>(adj, out);
}

// round 17
// speedup vs baseline: 3.9014x; 1.1205x over previous
#include <cuda_runtime.h>
#include <cuda_fp16.h>
#include <cstdint>

#define BB   16
#define NN   1024
#define FIN  256
#define FOUT 256
#define NEG_INF_V -1000000000.0f
#define SLOPE_V    0.2f

// ---------------- scratch (__device__ globals; no allocations) --------------
__device__ __half g_Wh16hi[(size_t)BB * NN * FOUT];        // 32 MB
__device__ __half g_Wh16lo[(size_t)BB * NN * FOUT];        // 32 MB
__device__ float  g_f1[(size_t)BB * NN];
__device__ float  g_f2[(size_t)BB * NN];
__device__ float  g_f2max[BB];

// ---------------- family-generic PTX helpers (sm_80+: valid on compute_103) -
__device__ __forceinline__ uint32_t smem_u32(const void* p) {
    uint32_t a;
    asm("{ .reg .u64 t; cvta.to.shared.u64 t, %1; cvt.u32.u64 %0, t; }"
        : "=r"(a) : "l"(p));
    return a;
}
__device__ __forceinline__ void ldsm4(uint32_t* r, uint32_t addr) {
    asm volatile("ldmatrix.sync.aligned.m8n8.x4.shared.b16 {%0,%1,%2,%3}, [%4];"
                 : "=r"(r[0]), "=r"(r[1]), "=r"(r[2]), "=r"(r[3]) : "r"(addr));
}
__device__ __forceinline__ void ldsm4t(uint32_t* r, uint32_t addr) {
    asm volatile("ldmatrix.sync.aligned.m8n8.x4.trans.shared.b16 {%0,%1,%2,%3}, [%4];"
                 : "=r"(r[0]), "=r"(r[1]), "=r"(r[2]), "=r"(r[3]) : "r"(addr));
}
__device__ __forceinline__ void mma_f16(float* d, const uint32_t* a,
                                        uint32_t b0, uint32_t b1) {
    asm volatile(
        "mma.sync.aligned.m16n8k16.row.col.f32.f16.f16.f32 "
        "{%0,%1,%2,%3}, {%4,%5,%6,%7}, {%8,%9}, {%0,%1,%2,%3};"
        : "+f"(d[0]), "+f"(d[1]), "+f"(d[2]), "+f"(d[3])
        : "r"(a[0]), "r"(a[1]), "r"(a[2]), "r"(a[3]), "r"(b0), "r"(b1));
}
__device__ __forceinline__ void cp_async16(uint32_t saddr, const void* gaddr) {
    asm volatile("cp.async.cg.shared.global [%0], [%1], 16;"
                 :: "r"(saddr), "l"(gaddr) : "memory");
}
#define CP_COMMIT() asm volatile("cp.async.commit_group;" ::: "memory")
#define CP_WAIT0()  asm volatile("cp.async.wait_group 0;" ::: "memory")

// split 8 fp32 -> packed hi/lo fp16 uint4s
__device__ __forceinline__ void split_pack8(const float* v, uint4& hv, uint4& lv) {
    __half hh[8], hl[8];
#pragma unroll
    for (int q = 0; q < 8; q++) {
        hh[q] = __float2half_rn(v[q]);
        hl[q] = __float2half_rn(v[q] - __half2float(hh[q]));
    }
    __half2 t0 = __halves2half2(hh[0], hh[1]), t1 = __halves2half2(hh[2], hh[3]);
    __half2 t2 = __halves2half2(hh[4], hh[5]), t3 = __halves2half2(hh[6], hh[7]);
    hv.x = *(uint32_t*)&t0; hv.y = *(uint32_t*)&t1;
    hv.z = *(uint32_t*)&t2; hv.w = *(uint32_t*)&t3;
    __half2 s0 = __halves2half2(hl[0], hl[1]), s1 = __halves2half2(hl[2], hl[3]);
    __half2 s2 = __halves2half2(hl[4], hl[5]), s3 = __halves2half2(hl[6], hl[7]);
    lv.x = *(uint32_t*)&s0; lv.y = *(uint32_t*)&s1;
    lv.z = *(uint32_t*)&s2; lv.w = *(uint32_t*)&s3;
}
// pack 8 fp32 -> fp16 (hi only)
__device__ __forceinline__ void pack8h(const float* v, uint4& hv) {
    __half2 t0 = __floats2half2_rn(v[0], v[1]);
    __half2 t1 = __floats2half2_rn(v[2], v[3]);
    __half2 t2 = __floats2half2_rn(v[4], v[5]);
    __half2 t3 = __floats2half2_rn(v[6], v[7]);
    hv.x = *(uint32_t*)&t0; hv.y = *(uint32_t*)&t1;
    hv.z = *(uint32_t*)&t2; hv.w = *(uint32_t*)&t3;
}

// ---------------------------------------------------------------------------
// Kernel 1: Wh = h @ W via mma.sync (3-term split), fp32 acc. Fused epilogue
// writes Wh16 hi/lo AND f1/f2. (R16-proven.)
// ---------------------------------------------------------------------------
#define S_WHI 0
#define S_WLO 16384
#define S_PHI 32768
#define S_PLO 36864
#define S_F12 0

__global__ __launch_bounds__(256, 2) void gemm_mma(const float* __restrict__ A,
                                                   const float* __restrict__ W,
                                                   const float* __restrict__ avec) {
    __shared__ __align__(16) unsigned char sm[40960];
    const uint32_t sb = smem_u32(sm);
    const int tid  = threadIdx.x;
    const int lane = tid & 31;
    const int wid  = tid >> 5;
    const int wm   = wid >> 2;
    const int wn   = wid & 3;
    const int i0   = blockIdx.x * 64;

    const int pr = tid >> 2, pc = tid & 3;
    const int jr = tid >> 3, cg = tid & 7;

    float acc[16][4];
#pragma unroll
    for (int n = 0; n < 16; n++)
#pragma unroll
        for (int q = 0; q < 4; q++) acc[n][q] = 0.f;

    for (int kt = 0; kt < 8; kt++) {
        const int k0 = kt * 32;
        {
            const float* wsrc = W + (size_t)(k0 + jr) * FOUT;
#pragma unroll
            for (int u = 0; u < 4; u++) {
                const int ch = u * 8 + cg;
                float v[8];
                *(float4*)&v[0] = *(const float4*)(wsrc + ch * 8);
                *(float4*)&v[4] = *(const float4*)(wsrc + ch * 8 + 4);
                uint4 hv, lv;
                split_pack8(v, hv, lv);
                const uint32_t so = (uint32_t)jr * 512 + ((ch ^ (jr & 7)) << 4);
                *(uint4*)(sm + S_WHI + so) = hv;
                *(uint4*)(sm + S_WLO + so) = lv;
            }
        }
        {
            const float* asrc = A + (size_t)(i0 + pr) * FIN + k0 + pc * 8;
            float v[8];
            *(float4*)&v[0] = *(const float4*)asrc;
            *(float4*)&v[4] = *(const float4*)(asrc + 4);
            uint4 hv, lv;
            split_pack8(v, hv, lv);
            const uint32_t po = (uint32_t)pr * 64 + ((pc ^ (pr & 3)) << 4);
            *(uint4*)(sm + S_PHI + po) = hv;
            *(uint4*)(sm + S_PLO + po) = lv;
        }
        __syncthreads();

#pragma unroll
        for (int k = 0; k < 2; k++) {
            uint32_t ah[2][4], al[2][4];
#pragma unroll
            for (int mb = 0; mb < 2; mb++) {
                const int arow = wm * 32 + mb * 16 + (lane & 15);
                const int ach  = k * 2 + (lane >> 4);
                const uint32_t ao = (uint32_t)arow * 64 + ((ach ^ (arow & 3)) << 4);
                ldsm4(ah[mb], sb + S_PHI + ao);
                ldsm4(al[mb], sb + S_PLO + ao);
            }
            const int brow = k * 16 + (lane & 15);
#pragma unroll
            for (int g = 0; g < 4; g++) {
                const int nc = wn * 8 + g * 2 + (lane >> 4);
                const uint32_t bo = (uint32_t)brow * 512 + ((nc ^ (brow & 7)) << 4);
                uint32_t bh[4], bl[4];
                ldsm4t(bh, sb + S_WHI + bo);
                ldsm4t(bl, sb + S_WLO + bo);
#pragma unroll
                for (int mb = 0; mb < 2; mb++) {
                    float* d0 = acc[mb * 8 + g * 2];
                    float* d1 = acc[mb * 8 + g * 2 + 1];
                    mma_f16(d0, ah[mb], bh[0], bh[1]);
                    mma_f16(d1, ah[mb], bh[2], bh[3]);
                    mma_f16(d0, al[mb], bh[0], bh[1]);
                    mma_f16(d1, al[mb], bh[2], bh[3]);
                    mma_f16(d0, ah[mb], bl[0], bl[1]);
                    mma_f16(d1, ah[mb], bl[2], bl[3]);
                }
            }
        }
        __syncthreads();
    }

    // epilogue A: Wh16 hi/lo
#pragma unroll
    for (int mb = 0; mb < 2; mb++) {
        const int ra = wm * 32 + mb * 16 + (lane >> 2);
#pragma unroll
        for (int nf = 0; nf < 8; nf++) {
            const int col = wn * 64 + nf * 8 + (lane & 3) * 2;
            const float* d = acc[mb * 8 + nf];
#pragma unroll
            for (int hrow = 0; hrow < 2; hrow++) {
                const size_t off = (size_t)(i0 + ra + hrow * 8) * FOUT + col;
                const float v0 = d[hrow * 2], v1 = d[hrow * 2 + 1];
                const __half h0 = __float2half_rn(v0), h1 = __float2half_rn(v1);
                const __half l0 = __float2half_rn(v0 - __half2float(h0));
                const __half l1 = __float2half_rn(v1 - __half2float(h1));
                __half2 hp = __halves2half2(h0, h1);
                __half2 lp = __halves2half2(l0, l1);
                *(uint32_t*)(g_Wh16hi + off) = *(uint32_t*)&hp;
                *(uint32_t*)(g_Wh16lo + off) = *(uint32_t*)&lp;
            }
        }
    }

    // epilogue B: fused f1/f2
    float* sf = (float*)(sm + S_F12);
    if (tid < 128) sf[tid] = 0.f;
    __syncthreads();
#pragma unroll
    for (int mb = 0; mb < 2; mb++) {
#pragma unroll
        for (int hrow = 0; hrow < 2; hrow++) {
            float s1 = 0.f, s2 = 0.f;
#pragma unroll
            for (int nf = 0; nf < 8; nf++) {
                const int col = wn * 64 + nf * 8 + (lane & 3) * 2;
                const float* d = acc[mb * 8 + nf];
                s1 += d[hrow * 2] * avec[col] + d[hrow * 2 + 1] * avec[col + 1];
                s2 += d[hrow * 2] * avec[FOUT + col] +
                      d[hrow * 2 + 1] * avec[FOUT + col + 1];
            }
            s1 += __shfl_xor_sync(0xffffffffu, s1, 1);
            s1 += __shfl_xor_sync(0xffffffffu, s1, 2);
            s2 += __shfl_xor_sync(0xffffffffu, s2, 1);
            s2 += __shfl_xor_sync(0xffffffffu, s2, 2);
            if ((lane & 3) == 0) {
                const int row = wm * 32 + mb * 16 + hrow * 8 + (lane >> 2);
                atomicAdd(&sf[row * 2 + 0], s1);
                atomicAdd(&sf[row * 2 + 1], s2);
            }
        }
    }
    __syncthreads();
    if (tid < 64) {
        g_f1[i0 + tid] = sf[tid * 2 + 0];
        g_f2[i0 + tid] = sf[tid * 2 + 1];
    }
}

// ---------------------------------------------------------------------------
// Kernel 1c: per-batch f2 max (softmax shift uses the UNMASKED bound:
// m_i = leaky_relu(f1_i + max_j f2_j) >= true masked max; ratio p/lsum exact).
// ---------------------------------------------------------------------------
__global__ __launch_bounds__(256) void f2max_kernel() {
    __shared__ float red[8];
    const int b    = blockIdx.x;
    const int tid  = threadIdx.x;
    const int lane = tid & 31;
    const int wid  = tid >> 5;
    const float* f2b = g_f2 + (size_t)b * NN;
    float m = -3.0e38f;
#pragma unroll
    for (int k = 0; k < 4; k++) m = fmaxf(m, f2b[tid + 256 * k]);
#pragma unroll
    for (int off = 16; off; off >>= 1)
        m = fmaxf(m, __shfl_xor_sync(0xffffffffu, m, off));
    if (lane == 0) red[wid] = m;
    __syncthreads();
    if (tid == 0) {
        float mm = red[0];
#pragma unroll
        for (int w = 1; w < 8; w++) mm = fmaxf(mm, red[w]);
        g_f2max[b] = mm;
    }
}

// ---------------------------------------------------------------------------
// Kernel 2: warp-mma flash-GAT, 2-term, cp.async DOUBLE-BUFFERED Wh tiles.
// Dynamic SMEM: Wh buf0 32K | Wh buf1 32K | P 4K | lsum 256 = 69888 B.
// Loop: compute P(t) (overlaps in-flight cp.async of Wh(t)) -> wait+sync ->
// issue cp.async Wh(t+1) -> MMA(t) -> sync.
// ---------------------------------------------------------------------------
#define AB_WHI(k) ((uint32_t)(k) * 32768u)
#define AB_WLO(k) ((uint32_t)(k) * 32768u + 16384u)
#define A_P   65536u
#define A_LS  69632u
#define ATTN_SMEM 69888

__global__ __launch_bounds__(256, 2) void attn_mma(const int* __restrict__ adj,
                                                   float* __restrict__ out) {
    extern __shared__ __align__(16) unsigned char sm[];
    const uint32_t sb = smem_u32(sm);
    const int tid  = threadIdx.x;
    const int lane = tid & 31;
    const int wid  = tid >> 5;
    const int wm   = wid >> 2;      // 0..1 : 32-row block
    const int wn   = wid & 3;       // 0..3 : 64-col block
    const int b    = blockIdx.y;
    const int i0   = blockIdx.x * 64;

    const int pr = tid >> 2;        // P-compute row 0..63
    const int pc = tid & 3;         // chunk of 8 j within 32-j tile
    const float f1r = g_f1[(size_t)b * NN + i0 + pr];
    const float sM  = f1r + g_f2max[b];
    const float mr  = fmaxf(sM, SLOPE_V * sM);   // unmasked-max shift
    const int*   adjrow = adj + ((size_t)b * NN + i0 + pr) * NN;
    const float* f2b    = g_f2 + (size_t)b * NN;
    const __half* whH = g_Wh16hi + (size_t)b * NN * FOUT;
    const __half* whL = g_Wh16lo + (size_t)b * NN * FOUT;

    float acc[16][4];
#pragma unroll
    for (int n = 0; n < 16; n++)
#pragma unroll
        for (int q = 0; q < 4; q++) acc[n][q] = 0.f;
    float lsum = 0.f;

    const int jr = tid >> 3;        // Wh stage row 0..31
    const int cg = tid & 7;         // col group

    // prologue: start Wh(0) copy
    {
        const __half* srcH = whH + (size_t)jr * FOUT;
        const __half* srcL = whL + (size_t)jr * FOUT;
#pragma unroll
        for (int u = 0; u < 4; u++) {
            const int ch = u * 8 + cg;
            const uint32_t so = (uint32_t)jr * 512 + ((ch ^ (jr & 7)) << 4);
            cp_async16(sb + AB_WHI(0) + so, srcH + ch * 8);
            cp_async16(sb + AB_WLO(0) + so, srcL + ch * 8);
        }
        CP_COMMIT();
    }

    for (int tile = 0; tile < 32; tile++) {
        const int buf = tile & 1;
        const int j0  = tile * 32;

        // ---- compute P(t): overlaps the in-flight cp.async ----
        {
            const int jj = j0 + pc * 8;
            const int4   a0 = *(const int4*)(adjrow + jj);
            const int4   a1 = *(const int4*)(adjrow + jj + 4);
            const float4 fA = *(const float4*)(f2b + jj);
            const float4 fB = *(const float4*)(f2b + jj + 4);
            const float sv[8] = {fA.x, fA.y, fA.z, fA.w, fB.x, fB.y, fB.z, fB.w};
            const int   mk[8] = {a0.x, a0.y, a0.z, a0.w, a1.x, a1.y, a1.z, a1.w};
            float p[8];
#pragma unroll
            for (int q = 0; q < 8; q++) {
                float s = f1r + sv[q];
                float e = fmaxf(s, SLOPE_V * s);
                if (mk[q] == 0) e = NEG_INF_V;
                p[q] = __expf(e - mr);
                lsum += p[q];
            }
            uint4 hv;
            pack8h(p, hv);
            const uint32_t po = (uint32_t)pr * 64 + ((pc ^ (pr & 3)) << 4);
            *(uint4*)(sm + A_P + po) = hv;
        }

        CP_WAIT0();            // Wh(t) arrived
        __syncthreads();       // P(t) + Wh(t) visible to all

        // ---- issue cp.async for Wh(t+1) into the other buffer ----
        if (tile < 31) {
            const int jn = (tile + 1) * 32;
            const __half* srcH = whH + (size_t)(jn + jr) * FOUT;
            const __half* srcL = whL + (size_t)(jn + jr) * FOUT;
            const uint32_t dH = AB_WHI(buf ^ 1), dL = AB_WLO(buf ^ 1);
#pragma unroll
            for (int u = 0; u < 4; u++) {
                const int ch = u * 8 + cg;
                const uint32_t so = (uint32_t)jr * 512 + ((ch ^ (jr & 7)) << 4);
                cp_async16(sb + dH + so, srcH + ch * 8);
                cp_async16(sb + dL + so, srcL + ch * 8);
            }
            CP_COMMIT();
        }

        // ---- MMA(t): 2 k16 x 2 mblk x 4 g x (2 terms x 2 n8) ----
        const uint32_t bWHI = AB_WHI(buf), bWLO = AB_WLO(buf);
#pragma unroll
        for (int k = 0; k < 2; k++) {
            uint32_t ah[2][4];
#pragma unroll
            for (int mb = 0; mb < 2; mb++) {
                const int arow = wm * 32 + mb * 16 + (lane & 15);
                const int ach  = k * 2 + (lane >> 4);
                const uint32_t ao = (uint32_t)arow * 64 + ((ach ^ (arow & 3)) << 4);
                ldsm4(ah[mb], sb + A_P + ao);
            }
            const int brow = k * 16 + (lane & 15);
#pragma unroll
            for (int g = 0; g < 4; g++) {
                const int nc = wn * 8 + g * 2 + (lane >> 4);
                const uint32_t bo = (uint32_t)brow * 512 + ((nc ^ (brow & 7)) << 4);
                uint32_t bh[4], bl[4];
                ldsm4t(bh, sb + bWHI + bo);
                ldsm4t(bl, sb + bWLO + bo);
#pragma unroll
                for (int mb = 0; mb < 2; mb++) {
                    float* d0 = acc[mb * 8 + g * 2];
                    float* d1 = acc[mb * 8 + g * 2 + 1];
                    mma_f16(d0, ah[mb], bh[0], bh[1]);
                    mma_f16(d1, ah[mb], bh[2], bh[3]);
                    mma_f16(d0, ah[mb], bl[0], bl[1]);
                    mma_f16(d1, ah[mb], bl[2], bl[3]);
                }
            }
        }
        __syncthreads();       // MMA(t) done: P buffer reusable next tile
    }

    // ---- lsum: reduce over the 4 threads sharing a row ----
    {
        float s = lsum;
        s += __shfl_xor_sync(0xffffffffu, s, 1);
        s += __shfl_xor_sync(0xffffffffu, s, 2);
        if (pc == 0) *(float*)(sm + A_LS + pr * 4) = s;
    }
    __syncthreads();

    // ---- epilogue: scale by 1/lsum, write ----
    float* outb = out + ((size_t)b * NN + i0) * FOUT;
#pragma unroll
    for (int mb = 0; mb < 2; mb++) {
        const int ra = wm * 32 + mb * 16 + (lane >> 2);
        const float ia = 1.f / *(float*)(sm + A_LS + ra * 4);
        const float ib = 1.f / *(float*)(sm + A_LS + (ra + 8) * 4);
#pragma unroll
        for (int nf = 0; nf < 8; nf++) {
            const int col = wn * 64 + nf * 8 + (lane & 3) * 2;
            const float* d = acc[mb * 8 + nf];
            *(float2*)(outb + (size_t)ra * FOUT + col) =
                make_float2(d[0] * ia, d[1] * ia);
            *(float2*)(outb + (size_t)(ra + 8) * FOUT + col) =
                make_float2(d[2] * ib, d[3] * ib);
        }
    }
}

// ---------------------------------------------------------------------------
extern "C" void kernel_launch(void* const* d_in, const int* in_sizes, int n_in,
                              void* d_out, int out_size) {
    const float* h   = (const float*)d_in[0];   // [16,1024,256] f32
    const int*   adj = (const int*)  d_in[1];   // [16,1024,1024] i32
    const float* W   = (const float*)d_in[2];   // [256,256] f32
    const float* a   = (const float*)d_in[3];   // [512] f32
    float* out = (float*)d_out;                 // [16,1024,256] f32

    cudaFuncSetAttribute(attn_mma, cudaFuncAttributeMaxDynamicSharedMemorySize,
                         ATTN_SMEM);

    gemm_mma<<<(BB * NN) / 64, 256>>>(h, W, a); // 256 blocks, f12 fused

    f2max_kernel<<<BB, 256>>>();                // per-batch unmasked f2 max

    dim3 g2(NN / 64, BB);                        // (16, 16)
    attn_mma<<<g2, 256, ATTN_SMEM>>>(adj, out);
}